// round 8
// baseline (speedup 1.0000x reference)
#include <cuda_runtime.h>
#include <cstdint>

// Branch-free 2-source encoding of the COEFFS table.
// Every program row has at most 2 nonzero coefficients.
// src selector: 0=h1, 1=h2, 2=r1, 3=r2. One-plane programs duplicate
// the source with coeff 0 (second load is an L1 hit -> no DRAM cost).
//
//  p : coeffs          -> (selA, cA, selB, cB)
//  0 : [ 1, 0, 0, 0]   -> (0, +1, 0,  0)
//  1 : [ 0, 0, 1, 0]   -> (2, +1, 2,  0)
//  2 : [ 1, 0, 1, 0]   -> (0, +1, 2, +1)
//  3 : [ 1, 1, 0, 0]   -> (0, +1, 1, +1)
//  4 : [ 0, 0, 1, 1]   -> (2, +1, 3, +1)
//  5 : [ 1,-1, 0, 0]   -> (0, +1, 1, -1)
//  6 : [ 1, 0,-1, 0]   -> (0, +1, 2, -1)
//  7 : [-1, 0, 1, 0]   -> (0, -1, 2, +1)
//  8 : [ 0, 0, 1,-1]   -> (2, +1, 3, -1)

__constant__ int PSEL[9][2] = {
    {0,0},{2,2},{0,2},{0,1},{2,3},{0,1},{0,2},{0,2},{2,3}
};
__constant__ float PC[9][2] = {
    { 1.f, 0.f},   // p0
    { 1.f, 0.f},   // p1
    { 1.f, 1.f},   // p2
    { 1.f, 1.f},   // p3
    { 1.f, 1.f},   // p4
    { 1.f,-1.f},   // p5
    { 1.f,-1.f},   // p6
    {-1.f, 1.f},   // p7
    { 1.f,-1.f}    // p8
};

// Persistent single-wave kernel: grid = 148 SMs x 5 resident CTAs = 740.
// Each CTA grid-strides over (b,s) pairs (~11 each), which removes the
// ~12 wave transitions of the 8192-block launch and averages out the
// 1-plane vs 2-plane per-pair load imbalance.
// Per pair: 256 threads x 4 float4; all 8 loads front-batched (MLP=8),
// evict-first (single-use streaming data).

__global__ __launch_bounds__(256, 5)
void tgm_kernel(const int* __restrict__ pid,
                const float* __restrict__ hearts,
                const float* __restrict__ rects,
                float* __restrict__ out,
                int pairs)
{
    const int t = threadIdx.x;

    for (int pair = blockIdx.x; pair < pairs; pair += gridDim.x)
    {
        const int p = __ldg(pid + pair);      // 0..8

        const int   sA = PSEL[p][0];
        const int   sB = PSEL[p][1];
        const float cA = PC[p][0];
        const float cB = PC[p][1];

        const size_t in_base = (size_t)pair * 8192;   // 2 planes per tensor

        const float* baseA = (sA < 2 ? hearts : rects) + in_base + (size_t)(sA & 1) * 4096;
        const float* baseB = (sB < 2 ? hearts : rects) + in_base + (size_t)(sB & 1) * 4096;

        const float4* A = (const float4*)baseA;
        const float4* B = (const float4*)baseB;
        float4*       O = (float4*)(out + (size_t)pair * 4096);

        // Front-batch all 8 loads.
        float4 va[4], vb[4];
        #pragma unroll
        for (int u = 0; u < 4; ++u) va[u] = __ldcs(&A[t + u * 256]);
        #pragma unroll
        for (int u = 0; u < 4; ++u) vb[u] = __ldcs(&B[t + u * 256]);

        #pragma unroll
        for (int u = 0; u < 4; ++u) {
            float4 r;
            r.x = __saturatef(fmaf(cB, vb[u].x, cA * va[u].x));
            r.y = __saturatef(fmaf(cB, vb[u].y, cA * va[u].y));
            r.z = __saturatef(fmaf(cB, vb[u].z, cA * va[u].z));
            r.w = __saturatef(fmaf(cB, vb[u].w, cA * va[u].w));
            __stcs(&O[t + u * 256], r);
        }
    }
}

extern "C" void kernel_launch(void* const* d_in, const int* in_sizes, int n_in,
                              void* d_out, int out_size)
{
    const int*   pid    = (const int*)  d_in[0];   // program_id  (128*64)
    const float* hearts = (const float*)d_in[1];   // (128,64,2,64,64)
    const float* rects  = (const float*)d_in[2];   // (128,64,2,64,64)
    float*       out    = (float*)d_out;           // (128,64,64,64)

    const int pairs = in_sizes[0];                 // 8192

    // One full wave: 148 SMs x 5 CTAs/SM (matches __launch_bounds__ occupancy).
    int grid = 148 * 5;
    if (grid > pairs) grid = pairs;

    tgm_kernel<<<grid, 256>>>(pid, hearts, rects, out, pairs);
}

// round 9
// speedup vs baseline: 1.0701x; 1.0701x over previous
#include <cuda_runtime.h>
#include <cstdint>

// Branch-free 2-source encoding of the COEFFS table.
// Every program row has at most 2 nonzero coefficients.
// src selector: 0=h1, 1=h2, 2=r1, 3=r2. One-plane programs duplicate
// the source with coeff 0 (second load is an L1 hit -> no DRAM cost).
//
//  p : coeffs          -> (selA, cA, selB, cB)
//  0 : [ 1, 0, 0, 0]   -> (0, +1, 0,  0)
//  1 : [ 0, 0, 1, 0]   -> (2, +1, 2,  0)
//  2 : [ 1, 0, 1, 0]   -> (0, +1, 2, +1)
//  3 : [ 1, 1, 0, 0]   -> (0, +1, 1, +1)
//  4 : [ 0, 0, 1, 1]   -> (2, +1, 3, +1)
//  5 : [ 1,-1, 0, 0]   -> (0, +1, 1, -1)
//  6 : [ 1, 0,-1, 0]   -> (0, +1, 2, -1)
//  7 : [-1, 0, 1, 0]   -> (0, -1, 2, +1)
//  8 : [ 0, 0, 1,-1]   -> (2, +1, 3, -1)

__constant__ int PSEL[9][2] = {
    {0,0},{2,2},{0,2},{0,1},{2,3},{0,1},{0,2},{0,2},{2,3}
};
__constant__ float PC[9][2] = {
    { 1.f, 0.f},   // p0
    { 1.f, 0.f},   // p1
    { 1.f, 1.f},   // p2
    { 1.f, 1.f},   // p3
    { 1.f, 1.f},   // p4
    { 1.f,-1.f},   // p5
    { 1.f,-1.f},   // p6
    {-1.f, 1.f},   // p7
    { 1.f,-1.f}    // p8
};

// One block per (b,s) pair (8192 blocks): fine-grained blocks let the HW
// scheduler dynamically load-balance the 1-plane vs 2-plane programs —
// measured faster than a persistent grid (R8: static 11-vs-12 iteration
// tail cost ~5%). 256 threads x 4 float4; all 8 loads front-batched
// (MLP=8), evict-first streaming hints (data is single-use).

__global__ __launch_bounds__(256, 5)
void tgm_kernel(const int* __restrict__ pid,
                const float* __restrict__ hearts,
                const float* __restrict__ rects,
                float* __restrict__ out)
{
    const int pair = blockIdx.x;              // 0..8191
    const int p    = __ldg(pid + pair);       // 0..8

    const int   sA = PSEL[p][0];
    const int   sB = PSEL[p][1];
    const float cA = PC[p][0];
    const float cB = PC[p][1];

    const size_t in_base = (size_t)pair * 8192;   // 2 planes per tensor

    const float* baseA = (sA < 2 ? hearts : rects) + in_base + (size_t)(sA & 1) * 4096;
    const float* baseB = (sB < 2 ? hearts : rects) + in_base + (size_t)(sB & 1) * 4096;

    const float4* A = (const float4*)baseA;
    const float4* B = (const float4*)baseB;
    float4*       O = (float4*)(out + (size_t)pair * 4096);

    const int t = threadIdx.x;

    // Front-batch all 8 loads (evict-first: single-use streaming data).
    float4 va[4], vb[4];
    #pragma unroll
    for (int u = 0; u < 4; ++u) va[u] = __ldcs(&A[t + u * 256]);
    #pragma unroll
    for (int u = 0; u < 4; ++u) vb[u] = __ldcs(&B[t + u * 256]);

    #pragma unroll
    for (int u = 0; u < 4; ++u) {
        float4 r;
        r.x = __saturatef(fmaf(cB, vb[u].x, cA * va[u].x));
        r.y = __saturatef(fmaf(cB, vb[u].y, cA * va[u].y));
        r.z = __saturatef(fmaf(cB, vb[u].z, cA * va[u].z));
        r.w = __saturatef(fmaf(cB, vb[u].w, cA * va[u].w));
        __stcs(&O[t + u * 256], r);
    }
}

extern "C" void kernel_launch(void* const* d_in, const int* in_sizes, int n_in,
                              void* d_out, int out_size)
{
    const int*   pid    = (const int*)  d_in[0];   // program_id  (128*64)
    const float* hearts = (const float*)d_in[1];   // (128,64,2,64,64)
    const float* rects  = (const float*)d_in[2];   // (128,64,2,64,64)
    float*       out    = (float*)d_out;           // (128,64,64,64)

    const int pairs = in_sizes[0];                 // 8192
    tgm_kernel<<<pairs, 256>>>(pid, hearts, rects, out);
}